// round 13
// baseline (speedup 1.0000x reference)
#include <cuda_runtime.h>
#include <cuda_fp16.h>

#define N_NODES 100000
#define N_EDGES 1600000
#define D       128
#define LN_EPS  1e-5f
#define CAP     96          // per-node bucket capacity; P(deg>96) ~ 1e-40

// ------- scratch (device globals; zero-initialized at load) -------
__device__ int    g_cnt[N_NODES];             // degrees; built by scatter, reset by layer1
__device__ int2   g_edge[N_NODES * CAP];      // padded buckets: (src, val as dup half2), 76.8 MB
__device__ __half g_xh[N_NODES * D];          // fp16 copy of x   (25.6 MB)
__device__ __half g_h[N_NODES * D];           // fp16 layer-0 out (25.6 MB)

// ---------------------------------------------------------------
// single kernel builds the bucketed edge list AND converts x->fp16.
// slot = atomicAdd(&cnt[dst], 1) is both the histogram and the offset.
// cvt's DRAM stream hides in the atomic-latency shadow.
// ---------------------------------------------------------------
__global__ void k_scatter_cvt(const int* __restrict__ src,
                              const int* __restrict__ dst,
                              const float* __restrict__ val,
                              const float* __restrict__ x) {
    int e = blockIdx.x * blockDim.x + threadIdx.x;
    int gsz = gridDim.x * blockDim.x;

    // cvt: grid-stride over 3.2M float4 (~2 per thread at this grid size)
    const float4* x4 = (const float4*)x;
    uint2* o2 = (uint2*)g_xh;
    for (int i = e; i < N_NODES * D / 4; i += gsz) {
        float4 v = x4[i];
        __half2 lo = __floats2half2_rn(v.x, v.y);
        __half2 hi = __floats2half2_rn(v.z, v.w);
        uint2 p;
        p.x = *(unsigned int*)&lo;
        p.y = *(unsigned int*)&hi;
        o2[i] = p;
    }

    // bucket scatter: one edge per thread (frozen access pattern)
    if (e < N_EDGES) {
        int   d = dst[e];
        int   s = src[e];
        float v = val[e];
        __half2 vh = __float2half2_rn(v);          // duplicated half2
        int p = atomicAdd(&g_cnt[d], 1);
        if (p < CAP)                               // memory-safety guard
            g_edge[d * CAP + p] = make_int2(s, (int)*(unsigned int*)&vh);
    }
}

// ---------------------------------------------------------------
// fused gather(fp16)-aggregate + diag-scale + LayerNorm (+ReLU)
// one warp per node; lane l owns features [4l, 4l+4).
// Edge pairs combined in fp16 (HMUL2/HFMA2), fp32 accumulation.
// Loop body R10 form — FROZEN (R4/R7/R11 alternatives regressed).
// ---------------------------------------------------------------
__device__ __forceinline__ __half2 as_h2(unsigned int u) { return *(__half2*)&u; }

template <bool RELU, bool OUT_HALF, bool RESET_CNT>
__device__ __forceinline__ void agg_node(const __half* __restrict__ in,
                                         const float* __restrict__ w,
                                         const float* __restrict__ gam,
                                         const float* __restrict__ bet,
                                         void* __restrict__ out) {
    int node = (blockIdx.x * blockDim.x + threadIdx.x) >> 5;
    int lane = threadIdx.x & 31;
    if (node >= N_NODES) return;

    int deg = g_cnt[node];
    if (deg > CAP) deg = CAP;
    int beg = node * CAP;
    int end = beg + deg;

    if (RESET_CNT && lane == 0) g_cnt[node] = 0;   // reset AFTER last reader (layer1)

    float4 acc = make_float4(0.f, 0.f, 0.f, 0.f);
    const uint2* in2 = (const uint2*)in;

    int e = beg;
    for (; e + 4 <= end; e += 4) {
        int2 e0 = g_edge[e],     e1 = g_edge[e + 1];
        int2 e2 = g_edge[e + 2], e3 = g_edge[e + 3];
        uint2 x0 = in2[e0.x * 32 + lane];
        uint2 x1 = in2[e1.x * 32 + lane];
        uint2 x2 = in2[e2.x * 32 + lane];
        uint2 x3 = in2[e3.x * 32 + lane];
        __half2 v0 = as_h2((unsigned int)e0.y), v1 = as_h2((unsigned int)e1.y);
        __half2 v2 = as_h2((unsigned int)e2.y), v3 = as_h2((unsigned int)e3.y);

        __half2 q0 = __hmul2(as_h2(x0.x), v0);
        q0 = __hfma2(as_h2(x1.x), v1, q0);
        __half2 q1 = __hmul2(as_h2(x0.y), v0);
        q1 = __hfma2(as_h2(x1.y), v1, q1);
        __half2 r0 = __hmul2(as_h2(x2.x), v2);
        r0 = __hfma2(as_h2(x3.x), v3, r0);
        __half2 r1 = __hmul2(as_h2(x2.y), v2);
        r1 = __hfma2(as_h2(x3.y), v3, r1);

        float2 f;
        f = __half22float2(q0); acc.x += f.x; acc.y += f.y;
        f = __half22float2(q1); acc.z += f.x; acc.w += f.y;
        f = __half22float2(r0); acc.x += f.x; acc.y += f.y;
        f = __half22float2(r1); acc.z += f.x; acc.w += f.y;
    }
    if (e + 2 <= end) {
        int2 e0 = g_edge[e], e1 = g_edge[e + 1];
        uint2 x0 = in2[e0.x * 32 + lane];
        uint2 x1 = in2[e1.x * 32 + lane];
        __half2 v0 = as_h2((unsigned int)e0.y), v1 = as_h2((unsigned int)e1.y);
        __half2 q0 = __hmul2(as_h2(x0.x), v0);
        q0 = __hfma2(as_h2(x1.x), v1, q0);
        __half2 q1 = __hmul2(as_h2(x0.y), v0);
        q1 = __hfma2(as_h2(x1.y), v1, q1);
        float2 f;
        f = __half22float2(q0); acc.x += f.x; acc.y += f.y;
        f = __half22float2(q1); acc.z += f.x; acc.w += f.y;
        e += 2;
    }
    if (e < end) {
        int2 ed = g_edge[e];
        uint2 x0 = in2[ed.x * 32 + lane];
        __half2 v = as_h2((unsigned int)ed.y);
        __half2 q0 = __hmul2(as_h2(x0.x), v);
        __half2 q1 = __hmul2(as_h2(x0.y), v);
        float2 f;
        f = __half22float2(q0); acc.x += f.x; acc.y += f.y;
        f = __half22float2(q1); acc.z += f.x; acc.w += f.y;
    }

    // diag transform: t = acc * w
    float4 w4 = ((const float4*)w)[lane];
    float4 t;
    t.x = acc.x * w4.x; t.y = acc.y * w4.y;
    t.z = acc.z * w4.z; t.w = acc.w * w4.w;

    // LayerNorm via warp reduce
    float sm = t.x + t.y + t.z + t.w;
    float sq = t.x * t.x + t.y * t.y + t.z * t.z + t.w * t.w;
    #pragma unroll
    for (int o = 16; o; o >>= 1) {
        sm += __shfl_xor_sync(0xffffffffu, sm, o);
        sq += __shfl_xor_sync(0xffffffffu, sq, o);
    }
    float mu  = sm * (1.f / D);
    float var = sq * (1.f / D) - mu * mu;
    float rs  = rsqrtf(var + LN_EPS);

    float4 g4 = ((const float4*)gam)[lane];
    float4 b4 = ((const float4*)bet)[lane];
    float4 o4;
    o4.x = fmaf((t.x - mu) * rs, g4.x, b4.x);
    o4.y = fmaf((t.y - mu) * rs, g4.y, b4.y);
    o4.z = fmaf((t.z - mu) * rs, g4.z, b4.z);
    o4.w = fmaf((t.w - mu) * rs, g4.w, b4.w);
    if (RELU) {
        o4.x = fmaxf(o4.x, 0.f); o4.y = fmaxf(o4.y, 0.f);
        o4.z = fmaxf(o4.z, 0.f); o4.w = fmaxf(o4.w, 0.f);
    }

    if (OUT_HALF) {
        __half2 lo = __floats2half2_rn(o4.x, o4.y);
        __half2 hi = __floats2half2_rn(o4.z, o4.w);
        uint2 p;
        p.x = *(unsigned int*)&lo;
        p.y = *(unsigned int*)&hi;
        ((uint2*)out)[node * 32 + lane] = p;
    } else {
        ((float4*)out)[node * 32 + lane] = o4;
    }
}

__global__ void k_layer0(const float* __restrict__ w,
                         const float* __restrict__ gam,
                         const float* __restrict__ bet) {
    agg_node<true, true, false>(g_xh, w, gam, bet, (void*)g_h);
}

__global__ void k_layer1(const float* __restrict__ w,
                         const float* __restrict__ gam,
                         const float* __restrict__ bet,
                         float* __restrict__ out) {
    agg_node<false, false, true>(g_h, w, gam, bet, (void*)out);   // resets g_cnt
}

// ---------------------------------------------------------------
extern "C" void kernel_launch(void* const* d_in, const int* in_sizes, int n_in,
                              void* d_out, int out_size) {
    const float* x     = (const float*)d_in[0];
    const int*   esrc  = (const int*)  d_in[1];
    const int*   edst  = (const int*)  d_in[2];
    const float* eval_ = (const float*)d_in[3];
    const float* w1    = (const float*)d_in[4];
    const float* w2    = (const float*)d_in[5];
    const float* ln1g  = (const float*)d_in[6];
    const float* ln1b  = (const float*)d_in[7];
    const float* ln2g  = (const float*)d_in[8];
    const float* ln2b  = (const float*)d_in[9];
    float* out = (float*)d_out;

    k_scatter_cvt<<<(N_EDGES + 255) / 256, 256>>>(esrc, edst, eval_, x);

    int blocks = (N_NODES * 32 + 255) / 256;
    k_layer0<<<blocks, 256>>>(w1, ln1g, ln1b);
    k_layer1<<<blocks, 256>>>(w2, ln2g, ln2b, out);
}

// round 14
// speedup vs baseline: 2.1460x; 2.1460x over previous
#include <cuda_runtime.h>
#include <cuda_fp16.h>

#define N_NODES 100000
#define N_EDGES 1600000
#define D       128
#define LN_EPS  1e-5f

// lookback scan config
#define TILE_THREADS 256
#define ITEMS        16
#define SCAN_TILE    (TILE_THREADS * ITEMS)                  // 4096
#define N_TILES      ((N_NODES + SCAN_TILE - 1) / SCAN_TILE) // 25

// ------- scratch (device globals; zero-initialized at load) -------
__device__ int    g_cnt[N_NODES];          // degrees; reset by layer0 epilogue
__device__ int    g_rowptr[N_NODES + 1];   // exclusive prefix; [N] set by scatter
__device__ int    g_cursor[N_NODES];       // scan writes prefix; scatter consumes
__device__ int    g_tstate[N_TILES];       // reset by scatter (post-scan)
__device__ int    g_ticket;                // reset by scatter (post-scan)
__device__ int2   g_edge[N_EDGES];         // (src, val as duplicated half2) — 12.8MB dense
__device__ __half g_xh[N_NODES * D];       // fp16 copy of x   (25.6 MB)
__device__ __half g_h[N_NODES * D];        // fp16 layer-0 out (25.6 MB)

// ---------------------------------------------------------------
// degree histogram only (atomic results discarded -> REDG no-return)
// ---------------------------------------------------------------
__global__ void k_hist(const int* __restrict__ dst) {
    int tid = blockIdx.x * blockDim.x + threadIdx.x;
    int gsz = gridDim.x * blockDim.x;
    const int4* d4 = (const int4*)dst;
    for (int i = tid; i < N_EDGES / 4; i += gsz) {
        int4 d = d4[i];
        atomicAdd(&g_cnt[d.x], 1);
        atomicAdd(&g_cnt[d.y], 1);
        atomicAdd(&g_cnt[d.z], 1);
        atomicAdd(&g_cnt[d.w], 1);
    }
}

// ---------------------------------------------------------------
// single-pass exclusive scan (decoupled lookback): g_cnt -> g_rowptr
// ALSO writes the same prefix into g_cursor (scatter's atomic base)
// ---------------------------------------------------------------
__global__ void __launch_bounds__(TILE_THREADS) k_scan() {
    __shared__ int sh_warp[TILE_THREADS / 32];
    __shared__ int sh_prev;
    __shared__ int sh_tile;

    int t = threadIdx.x;
    if (t == 0) sh_tile = atomicAdd(&g_ticket, 1);
    __syncthreads();
    int tile = sh_tile;
    int base = tile * SCAN_TILE + t * ITEMS;

    int v[ITEMS];
    #pragma unroll
    for (int i = 0; i < ITEMS; i += 4) {
        int idx = base + i;
        int4 c;
        if (idx + 3 < N_NODES) {
            c = *(const int4*)&g_cnt[idx];
        } else {
            c.x = (idx     < N_NODES) ? g_cnt[idx]     : 0;
            c.y = (idx + 1 < N_NODES) ? g_cnt[idx + 1] : 0;
            c.z = (idx + 2 < N_NODES) ? g_cnt[idx + 2] : 0;
            c.w = (idx + 3 < N_NODES) ? g_cnt[idx + 3] : 0;
        }
        v[i] = c.x; v[i + 1] = c.y; v[i + 2] = c.z; v[i + 3] = c.w;
    }
    #pragma unroll
    for (int i = 1; i < ITEMS; i++) v[i] += v[i - 1];

    int tot = v[ITEMS - 1];
    int lane = t & 31, wid = t >> 5;
    int s = tot;
    #pragma unroll
    for (int o = 1; o < 32; o <<= 1) {
        int n = __shfl_up_sync(0xffffffffu, s, o);
        if (lane >= o) s += n;
    }
    if (lane == 31) sh_warp[wid] = s;
    __syncthreads();
    if (wid == 0) {
        int ws = (lane < TILE_THREADS / 32) ? sh_warp[lane] : 0;
        #pragma unroll
        for (int o = 1; o < TILE_THREADS / 32; o <<= 1) {
            int n = __shfl_up_sync(0xffffffffu, ws, o);
            if (lane >= o) ws += n;
        }
        if (lane < TILE_THREADS / 32) sh_warp[lane] = ws;
    }
    __syncthreads();
    int thr_excl  = (wid > 0 ? sh_warp[wid - 1] : 0) + (s - tot);
    int block_tot = sh_warp[TILE_THREADS / 32 - 1];

    if (t == 0) {
        if (tile == 0) {
            __threadfence();
            atomicExch(&g_tstate[0], (block_tot << 2) | 2);
            sh_prev = 0;
        } else {
            __threadfence();
            atomicExch(&g_tstate[tile], (block_tot << 2) | 1);
            int prev = 0;
            int j = tile - 1;
            while (true) {
                int st = atomicAdd(&g_tstate[j], 0);
                int f = st & 3;
                if (f == 2) { prev += st >> 2; break; }
                if (f == 1) { prev += st >> 2; j--; }
            }
            __threadfence();
            atomicExch(&g_tstate[tile], ((prev + block_tot) << 2) | 2);
            sh_prev = prev;
        }
    }
    __syncthreads();
    int excl = sh_prev + thr_excl;

    #pragma unroll
    for (int i = 0; i < ITEMS; i += 4) {
        int idx = base + i;
        int4 o;
        o.x = excl + (i > 0 ? v[i - 1] : 0);
        o.y = excl + v[i];
        o.z = excl + v[i + 1];
        o.w = excl + v[i + 2];
        if (idx + 3 < N_NODES) {
            *(int4*)&g_rowptr[idx] = o;
            *(int4*)&g_cursor[idx] = o;
        } else {
            if (idx     < N_NODES) { g_rowptr[idx]     = o.x; g_cursor[idx]     = o.x; }
            if (idx + 1 < N_NODES) { g_rowptr[idx + 1] = o.y; g_cursor[idx + 1] = o.y; }
            if (idx + 2 < N_NODES) { g_rowptr[idx + 2] = o.z; g_cursor[idx + 2] = o.z; }
            if (idx + 3 < N_NODES) { g_rowptr[idx + 3] = o.w; g_cursor[idx + 3] = o.w; }
        }
    }
}

// ---------------------------------------------------------------
// scatter (one edge/thread) FUSED with fp32->fp16 cvt of x.
// x read with evict-first (__ldcs): streamed exactly once.
// Stores val as DUPLICATED half2. Also resets scan state for replay.
// ---------------------------------------------------------------
__global__ void k_scatter_cvt(const int* __restrict__ src,
                              const int* __restrict__ dst,
                              const float* __restrict__ val,
                              const float* __restrict__ x) {
    int e = blockIdx.x * blockDim.x + threadIdx.x;
    int gsz = gridDim.x * blockDim.x;

    if (e < N_TILES) g_tstate[e] = 0;                 // post-scan reset
    if (e == N_TILES)     g_ticket = 0;
    if (e == N_TILES + 1) g_rowptr[N_NODES] = N_EDGES;

    // cvt: grid-stride over 3.2M float4 (~2 per thread at this grid size)
    const float4* x4 = (const float4*)x;
    uint2* o2 = (uint2*)g_xh;
    for (int i = e; i < N_NODES * D / 4; i += gsz) {
        float4 v = __ldcs(&x4[i]);                    // evict-first: read-once stream
        __half2 lo = __floats2half2_rn(v.x, v.y);
        __half2 hi = __floats2half2_rn(v.z, v.w);
        uint2 p;
        p.x = *(unsigned int*)&lo;
        p.y = *(unsigned int*)&hi;
        o2[i] = p;
    }

    // scatter: p = atomicAdd(cursor[d]) is the absolute CSR slot
    if (e < N_EDGES) {
        int   d = dst[e];
        int   s = src[e];
        float v = val[e];
        __half2 vh = __float2half2_rn(v);             // duplicated half2
        int p = atomicAdd(&g_cursor[d], 1);
        g_edge[p] = make_int2(s, (int)*(unsigned int*)&vh);
    }
}

// ---------------------------------------------------------------
// fused gather(fp16)-aggregate + diag-scale + LayerNorm (+ReLU)
// one warp per node; lane l owns features [4l, 4l+4).
// Edge pairs combined in fp16 (HMUL2/HFMA2), fp32 accumulation.
// Loop body R10 form — FROZEN. Final fp32 out stored with __stcs
// (write-once stream; keeps g_h/edges L2-resident).
// ---------------------------------------------------------------
__device__ __forceinline__ __half2 as_h2(unsigned int u) { return *(__half2*)&u; }

template <bool RELU, bool OUT_HALF, bool RESET_CNT>
__device__ __forceinline__ void agg_node(const __half* __restrict__ in,
                                         const float* __restrict__ w,
                                         const float* __restrict__ gam,
                                         const float* __restrict__ bet,
                                         void* __restrict__ out) {
    int node = (blockIdx.x * blockDim.x + threadIdx.x) >> 5;
    int lane = threadIdx.x & 31;
    if (node >= N_NODES) return;

    int beg = g_rowptr[node];
    int end = g_rowptr[node + 1];

    if (RESET_CNT && lane == 0) g_cnt[node] = 0;   // state reset for next replay

    float4 acc = make_float4(0.f, 0.f, 0.f, 0.f);
    const uint2* in2 = (const uint2*)in;

    int e = beg;
    for (; e + 4 <= end; e += 4) {
        int2 e0 = g_edge[e],     e1 = g_edge[e + 1];
        int2 e2 = g_edge[e + 2], e3 = g_edge[e + 3];
        uint2 x0 = in2[e0.x * 32 + lane];
        uint2 x1 = in2[e1.x * 32 + lane];
        uint2 x2 = in2[e2.x * 32 + lane];
        uint2 x3 = in2[e3.x * 32 + lane];
        __half2 v0 = as_h2((unsigned int)e0.y), v1 = as_h2((unsigned int)e1.y);
        __half2 v2 = as_h2((unsigned int)e2.y), v3 = as_h2((unsigned int)e3.y);

        __half2 q0 = __hmul2(as_h2(x0.x), v0);
        q0 = __hfma2(as_h2(x1.x), v1, q0);
        __half2 q1 = __hmul2(as_h2(x0.y), v0);
        q1 = __hfma2(as_h2(x1.y), v1, q1);
        __half2 r0 = __hmul2(as_h2(x2.x), v2);
        r0 = __hfma2(as_h2(x3.x), v3, r0);
        __half2 r1 = __hmul2(as_h2(x2.y), v2);
        r1 = __hfma2(as_h2(x3.y), v3, r1);

        float2 f;
        f = __half22float2(q0); acc.x += f.x; acc.y += f.y;
        f = __half22float2(q1); acc.z += f.x; acc.w += f.y;
        f = __half22float2(r0); acc.x += f.x; acc.y += f.y;
        f = __half22float2(r1); acc.z += f.x; acc.w += f.y;
    }
    if (e + 2 <= end) {
        int2 e0 = g_edge[e], e1 = g_edge[e + 1];
        uint2 x0 = in2[e0.x * 32 + lane];
        uint2 x1 = in2[e1.x * 32 + lane];
        __half2 v0 = as_h2((unsigned int)e0.y), v1 = as_h2((unsigned int)e1.y);
        __half2 q0 = __hmul2(as_h2(x0.x), v0);
        q0 = __hfma2(as_h2(x1.x), v1, q0);
        __half2 q1 = __hmul2(as_h2(x0.y), v0);
        q1 = __hfma2(as_h2(x1.y), v1, q1);
        float2 f;
        f = __half22float2(q0); acc.x += f.x; acc.y += f.y;
        f = __half22float2(q1); acc.z += f.x; acc.w += f.y;
        e += 2;
    }
    if (e < end) {
        int2 ed = g_edge[e];
        uint2 x0 = in2[ed.x * 32 + lane];
        __half2 v = as_h2((unsigned int)ed.y);
        __half2 q0 = __hmul2(as_h2(x0.x), v);
        __half2 q1 = __hmul2(as_h2(x0.y), v);
        float2 f;
        f = __half22float2(q0); acc.x += f.x; acc.y += f.y;
        f = __half22float2(q1); acc.z += f.x; acc.w += f.y;
    }

    // diag transform: t = acc * w
    float4 w4 = ((const float4*)w)[lane];
    float4 t;
    t.x = acc.x * w4.x; t.y = acc.y * w4.y;
    t.z = acc.z * w4.z; t.w = acc.w * w4.w;

    // LayerNorm via warp reduce
    float sm = t.x + t.y + t.z + t.w;
    float sq = t.x * t.x + t.y * t.y + t.z * t.z + t.w * t.w;
    #pragma unroll
    for (int o = 16; o; o >>= 1) {
        sm += __shfl_xor_sync(0xffffffffu, sm, o);
        sq += __shfl_xor_sync(0xffffffffu, sq, o);
    }
    float mu  = sm * (1.f / D);
    float var = sq * (1.f / D) - mu * mu;
    float rs  = rsqrtf(var + LN_EPS);

    float4 g4 = ((const float4*)gam)[lane];
    float4 b4 = ((const float4*)bet)[lane];
    float4 o4;
    o4.x = fmaf((t.x - mu) * rs, g4.x, b4.x);
    o4.y = fmaf((t.y - mu) * rs, g4.y, b4.y);
    o4.z = fmaf((t.z - mu) * rs, g4.z, b4.z);
    o4.w = fmaf((t.w - mu) * rs, g4.w, b4.w);
    if (RELU) {
        o4.x = fmaxf(o4.x, 0.f); o4.y = fmaxf(o4.y, 0.f);
        o4.z = fmaxf(o4.z, 0.f); o4.w = fmaxf(o4.w, 0.f);
    }

    if (OUT_HALF) {
        __half2 lo = __floats2half2_rn(o4.x, o4.y);
        __half2 hi = __floats2half2_rn(o4.z, o4.w);
        uint2 p;
        p.x = *(unsigned int*)&lo;
        p.y = *(unsigned int*)&hi;
        ((uint2*)out)[node * 32 + lane] = p;      // g_h: re-read by layer1, keep cached
    } else {
        __stcs(&((float4*)out)[node * 32 + lane], o4);  // final out: write-once stream
    }
}

__global__ void k_layer0(const float* __restrict__ w,
                         const float* __restrict__ gam,
                         const float* __restrict__ bet) {
    agg_node<true, true, true>(g_xh, w, gam, bet, (void*)g_h);
}

__global__ void k_layer1(const float* __restrict__ w,
                         const float* __restrict__ gam,
                         const float* __restrict__ bet,
                         float* __restrict__ out) {
    agg_node<false, false, false>(g_h, w, gam, bet, (void*)out);
}

// ---------------------------------------------------------------
extern "C" void kernel_launch(void* const* d_in, const int* in_sizes, int n_in,
                              void* d_out, int out_size) {
    const float* x     = (const float*)d_in[0];
    const int*   esrc  = (const int*)  d_in[1];
    const int*   edst  = (const int*)  d_in[2];
    const float* eval_ = (const float*)d_in[3];
    const float* w1    = (const float*)d_in[4];
    const float* w2    = (const float*)d_in[5];
    const float* ln1g  = (const float*)d_in[6];
    const float* ln1b  = (const float*)d_in[7];
    const float* ln2g  = (const float*)d_in[8];
    const float* ln2b  = (const float*)d_in[9];
    float* out = (float*)d_out;

    k_hist<<<(N_EDGES / 4 + 255) / 256, 256>>>(edst);
    k_scan<<<N_TILES, TILE_THREADS>>>();
    k_scatter_cvt<<<(N_EDGES + 255) / 256, 256>>>(esrc, edst, eval_, x);

    int blocks = (N_NODES * 32 + 255) / 256;
    k_layer0<<<blocks, 256>>>(w1, ln1g, ln1b);
    k_layer1<<<blocks, 256>>>(w2, ln2g, ln2b, out);
}

// round 15
// speedup vs baseline: 2.2037x; 1.0269x over previous
#include <cuda_runtime.h>
#include <cuda_fp16.h>

#define N_NODES 100000
#define N_EDGES 1600000
#define D       128
#define LN_EPS  1e-5f

// lookback scan config
#define TILE_THREADS 256
#define ITEMS        16
#define SCAN_TILE    (TILE_THREADS * ITEMS)                  // 4096
#define N_TILES      ((N_NODES + SCAN_TILE - 1) / SCAN_TILE) // 25
#define HS_BLOCKS    200                                     // all co-resident

// ------- scratch (device globals; zero-initialized at load) -------
__device__ int    g_cnt[N_NODES];          // degrees; reset by layer0 epilogue
__device__ int    g_rowptr[N_NODES + 1];   // exclusive prefix; [N] set by scatter
__device__ int    g_cursor[N_NODES];       // scan writes prefix; scatter consumes
__device__ int    g_tstate[N_TILES];       // reset by scatter (post-scan)
__device__ int    g_bar;                   // grid barrier; reset by scatter
__device__ int2   g_edge[N_EDGES];         // (src, val as duplicated half2) — 12.8MB dense
__device__ __half g_xh[N_NODES * D];       // fp16 copy of x   (25.6 MB)
__device__ __half g_h[N_NODES * D];        // fp16 layer-0 out (25.6 MB)

// ---------------------------------------------------------------
// fused histogram + exclusive scan (persistent; internal grid barrier)
// Phase 1: all 200 blocks grid-stride REDG histogram.
// Phase 2: counter barrier (all blocks co-resident -> no deadlock).
// Phase 3: blocks 0..N_TILES-1 run the decoupled-lookback scan,
//          writing prefix into BOTH g_rowptr and g_cursor.
// ---------------------------------------------------------------
__global__ void __launch_bounds__(TILE_THREADS) k_hist_scan(const int* __restrict__ dst) {
    int t   = threadIdx.x;
    int gid = blockIdx.x * blockDim.x + t;
    int gsz = gridDim.x * blockDim.x;

    // ---- phase 1: histogram (results discarded -> REDG no-return) ----
    const int4* d4 = (const int4*)dst;
    for (int i = gid; i < N_EDGES / 4; i += gsz) {
        int4 d = d4[i];
        atomicAdd(&g_cnt[d.x], 1);
        atomicAdd(&g_cnt[d.y], 1);
        atomicAdd(&g_cnt[d.z], 1);
        atomicAdd(&g_cnt[d.w], 1);
    }

    // ---- phase 2: grid barrier ----
    __syncthreads();
    if (t == 0) {
        __threadfence();
        atomicAdd(&g_bar, 1);
        while (atomicAdd(&g_bar, 0) < HS_BLOCKS) { }
    }
    __syncthreads();

    // ---- phase 3: scan (first N_TILES blocks only) ----
    int tile = blockIdx.x;
    if (tile >= N_TILES) return;

    __shared__ int sh_warp[TILE_THREADS / 32];
    __shared__ int sh_prev;
    int base = tile * SCAN_TILE + t * ITEMS;

    int v[ITEMS];
    #pragma unroll
    for (int i = 0; i < ITEMS; i += 4) {
        int idx = base + i;
        int4 c;
        if (idx + 3 < N_NODES) {
            c = *(const int4*)&g_cnt[idx];
        } else {
            c.x = (idx     < N_NODES) ? g_cnt[idx]     : 0;
            c.y = (idx + 1 < N_NODES) ? g_cnt[idx + 1] : 0;
            c.z = (idx + 2 < N_NODES) ? g_cnt[idx + 2] : 0;
            c.w = (idx + 3 < N_NODES) ? g_cnt[idx + 3] : 0;
        }
        v[i] = c.x; v[i + 1] = c.y; v[i + 2] = c.z; v[i + 3] = c.w;
    }
    #pragma unroll
    for (int i = 1; i < ITEMS; i++) v[i] += v[i - 1];

    int tot = v[ITEMS - 1];
    int lane = t & 31, wid = t >> 5;
    int s = tot;
    #pragma unroll
    for (int o = 1; o < 32; o <<= 1) {
        int n = __shfl_up_sync(0xffffffffu, s, o);
        if (lane >= o) s += n;
    }
    if (lane == 31) sh_warp[wid] = s;
    __syncthreads();
    if (wid == 0) {
        int ws = (lane < TILE_THREADS / 32) ? sh_warp[lane] : 0;
        #pragma unroll
        for (int o = 1; o < TILE_THREADS / 32; o <<= 1) {
            int n = __shfl_up_sync(0xffffffffu, ws, o);
            if (lane >= o) ws += n;
        }
        if (lane < TILE_THREADS / 32) sh_warp[lane] = ws;
    }
    __syncthreads();
    int thr_excl  = (wid > 0 ? sh_warp[wid - 1] : 0) + (s - tot);
    int block_tot = sh_warp[TILE_THREADS / 32 - 1];

    if (t == 0) {
        if (tile == 0) {
            __threadfence();
            atomicExch(&g_tstate[0], (block_tot << 2) | 2);
            sh_prev = 0;
        } else {
            __threadfence();
            atomicExch(&g_tstate[tile], (block_tot << 2) | 1);
            int prev = 0;
            int j = tile - 1;
            while (true) {
                int st = atomicAdd(&g_tstate[j], 0);
                int f = st & 3;
                if (f == 2) { prev += st >> 2; break; }
                if (f == 1) { prev += st >> 2; j--; }
            }
            __threadfence();
            atomicExch(&g_tstate[tile], ((prev + block_tot) << 2) | 2);
            sh_prev = prev;
        }
    }
    __syncthreads();
    int excl = sh_prev + thr_excl;

    #pragma unroll
    for (int i = 0; i < ITEMS; i += 4) {
        int idx = base + i;
        int4 o;
        o.x = excl + (i > 0 ? v[i - 1] : 0);
        o.y = excl + v[i];
        o.z = excl + v[i + 1];
        o.w = excl + v[i + 2];
        if (idx + 3 < N_NODES) {
            *(int4*)&g_rowptr[idx] = o;
            *(int4*)&g_cursor[idx] = o;
        } else {
            if (idx     < N_NODES) { g_rowptr[idx]     = o.x; g_cursor[idx]     = o.x; }
            if (idx + 1 < N_NODES) { g_rowptr[idx + 1] = o.y; g_cursor[idx + 1] = o.y; }
            if (idx + 2 < N_NODES) { g_rowptr[idx + 2] = o.z; g_cursor[idx + 2] = o.z; }
            if (idx + 3 < N_NODES) { g_rowptr[idx + 3] = o.w; g_cursor[idx + 3] = o.w; }
        }
    }
}

// ---------------------------------------------------------------
// scatter (one edge/thread) FUSED with fp32->fp16 cvt of x.
// x read with evict-first (__ldcs): streamed exactly once.
// Stores val as DUPLICATED half2. Also resets scan state for replay.
// ---------------------------------------------------------------
__global__ void k_scatter_cvt(const int* __restrict__ src,
                              const int* __restrict__ dst,
                              const float* __restrict__ val,
                              const float* __restrict__ x) {
    int e = blockIdx.x * blockDim.x + threadIdx.x;
    int gsz = gridDim.x * blockDim.x;

    if (e < N_TILES) g_tstate[e] = 0;                 // post-scan reset
    if (e == N_TILES)     g_bar = 0;
    if (e == N_TILES + 1) g_rowptr[N_NODES] = N_EDGES;

    // cvt: grid-stride over 3.2M float4 (~2 per thread at this grid size)
    const float4* x4 = (const float4*)x;
    uint2* o2 = (uint2*)g_xh;
    for (int i = e; i < N_NODES * D / 4; i += gsz) {
        float4 v = __ldcs(&x4[i]);                    // evict-first: read-once stream
        __half2 lo = __floats2half2_rn(v.x, v.y);
        __half2 hi = __floats2half2_rn(v.z, v.w);
        uint2 p;
        p.x = *(unsigned int*)&lo;
        p.y = *(unsigned int*)&hi;
        o2[i] = p;
    }

    // scatter: p = atomicAdd(cursor[d]) is the absolute CSR slot
    if (e < N_EDGES) {
        int   d = dst[e];
        int   s = src[e];
        float v = val[e];
        __half2 vh = __float2half2_rn(v);             // duplicated half2
        int p = atomicAdd(&g_cursor[d], 1);
        g_edge[p] = make_int2(s, (int)*(unsigned int*)&vh);
    }
}

// ---------------------------------------------------------------
// fused gather(fp16)-aggregate + diag-scale + LayerNorm (+ReLU)
// one warp per node; lane l owns features [4l, 4l+4).
// Edge pairs combined in fp16 (HMUL2/HFMA2), fp32 accumulation.
// Loop body R10 form — FROZEN.
// ---------------------------------------------------------------
__device__ __forceinline__ __half2 as_h2(unsigned int u) { return *(__half2*)&u; }

template <bool RELU, bool OUT_HALF, bool RESET_CNT>
__device__ __forceinline__ void agg_node(const __half* __restrict__ in,
                                         const float* __restrict__ w,
                                         const float* __restrict__ gam,
                                         const float* __restrict__ bet,
                                         void* __restrict__ out) {
    int node = (blockIdx.x * blockDim.x + threadIdx.x) >> 5;
    int lane = threadIdx.x & 31;
    if (node >= N_NODES) return;

    int beg = g_rowptr[node];
    int end = g_rowptr[node + 1];

    if (RESET_CNT && lane == 0) g_cnt[node] = 0;   // state reset for next replay

    float4 acc = make_float4(0.f, 0.f, 0.f, 0.f);
    const uint2* in2 = (const uint2*)in;

    int e = beg;
    for (; e + 4 <= end; e += 4) {
        int2 e0 = g_edge[e],     e1 = g_edge[e + 1];
        int2 e2 = g_edge[e + 2], e3 = g_edge[e + 3];
        uint2 x0 = in2[e0.x * 32 + lane];
        uint2 x1 = in2[e1.x * 32 + lane];
        uint2 x2 = in2[e2.x * 32 + lane];
        uint2 x3 = in2[e3.x * 32 + lane];
        __half2 v0 = as_h2((unsigned int)e0.y), v1 = as_h2((unsigned int)e1.y);
        __half2 v2 = as_h2((unsigned int)e2.y), v3 = as_h2((unsigned int)e3.y);

        __half2 q0 = __hmul2(as_h2(x0.x), v0);
        q0 = __hfma2(as_h2(x1.x), v1, q0);
        __half2 q1 = __hmul2(as_h2(x0.y), v0);
        q1 = __hfma2(as_h2(x1.y), v1, q1);
        __half2 r0 = __hmul2(as_h2(x2.x), v2);
        r0 = __hfma2(as_h2(x3.x), v3, r0);
        __half2 r1 = __hmul2(as_h2(x2.y), v2);
        r1 = __hfma2(as_h2(x3.y), v3, r1);

        float2 f;
        f = __half22float2(q0); acc.x += f.x; acc.y += f.y;
        f = __half22float2(q1); acc.z += f.x; acc.w += f.y;
        f = __half22float2(r0); acc.x += f.x; acc.y += f.y;
        f = __half22float2(r1); acc.z += f.x; acc.w += f.y;
    }
    if (e + 2 <= end) {
        int2 e0 = g_edge[e], e1 = g_edge[e + 1];
        uint2 x0 = in2[e0.x * 32 + lane];
        uint2 x1 = in2[e1.x * 32 + lane];
        __half2 v0 = as_h2((unsigned int)e0.y), v1 = as_h2((unsigned int)e1.y);
        __half2 q0 = __hmul2(as_h2(x0.x), v0);
        q0 = __hfma2(as_h2(x1.x), v1, q0);
        __half2 q1 = __hmul2(as_h2(x0.y), v0);
        q1 = __hfma2(as_h2(x1.y), v1, q1);
        float2 f;
        f = __half22float2(q0); acc.x += f.x; acc.y += f.y;
        f = __half22float2(q1); acc.z += f.x; acc.w += f.y;
        e += 2;
    }
    if (e < end) {
        int2 ed = g_edge[e];
        uint2 x0 = in2[ed.x * 32 + lane];
        __half2 v = as_h2((unsigned int)ed.y);
        __half2 q0 = __hmul2(as_h2(x0.x), v);
        __half2 q1 = __hmul2(as_h2(x0.y), v);
        float2 f;
        f = __half22float2(q0); acc.x += f.x; acc.y += f.y;
        f = __half22float2(q1); acc.z += f.x; acc.w += f.y;
    }

    // diag transform: t = acc * w
    float4 w4 = ((const float4*)w)[lane];
    float4 t;
    t.x = acc.x * w4.x; t.y = acc.y * w4.y;
    t.z = acc.z * w4.z; t.w = acc.w * w4.w;

    // LayerNorm via warp reduce
    float sm = t.x + t.y + t.z + t.w;
    float sq = t.x * t.x + t.y * t.y + t.z * t.z + t.w * t.w;
    #pragma unroll
    for (int o = 16; o; o >>= 1) {
        sm += __shfl_xor_sync(0xffffffffu, sm, o);
        sq += __shfl_xor_sync(0xffffffffu, sq, o);
    }
    float mu  = sm * (1.f / D);
    float var = sq * (1.f / D) - mu * mu;
    float rs  = rsqrtf(var + LN_EPS);

    float4 g4 = ((const float4*)gam)[lane];
    float4 b4 = ((const float4*)bet)[lane];
    float4 o4;
    o4.x = fmaf((t.x - mu) * rs, g4.x, b4.x);
    o4.y = fmaf((t.y - mu) * rs, g4.y, b4.y);
    o4.z = fmaf((t.z - mu) * rs, g4.z, b4.z);
    o4.w = fmaf((t.w - mu) * rs, g4.w, b4.w);
    if (RELU) {
        o4.x = fmaxf(o4.x, 0.f); o4.y = fmaxf(o4.y, 0.f);
        o4.z = fmaxf(o4.z, 0.f); o4.w = fmaxf(o4.w, 0.f);
    }

    if (OUT_HALF) {
        __half2 lo = __floats2half2_rn(o4.x, o4.y);
        __half2 hi = __floats2half2_rn(o4.z, o4.w);
        uint2 p;
        p.x = *(unsigned int*)&lo;
        p.y = *(unsigned int*)&hi;
        ((uint2*)out)[node * 32 + lane] = p;      // g_h: re-read by layer1, keep cached
    } else {
        __stcs(&((float4*)out)[node * 32 + lane], o4);  // final out: write-once stream
    }
}

__global__ void k_layer0(const float* __restrict__ w,
                         const float* __restrict__ gam,
                         const float* __restrict__ bet) {
    agg_node<true, true, true>(g_xh, w, gam, bet, (void*)g_h);
}

__global__ void k_layer1(const float* __restrict__ w,
                         const float* __restrict__ gam,
                         const float* __restrict__ bet,
                         float* __restrict__ out) {
    agg_node<false, false, false>(g_h, w, gam, bet, (void*)out);
}

// ---------------------------------------------------------------
extern "C" void kernel_launch(void* const* d_in, const int* in_sizes, int n_in,
                              void* d_out, int out_size) {
    const float* x     = (const float*)d_in[0];
    const int*   esrc  = (const int*)  d_in[1];
    const int*   edst  = (const int*)  d_in[2];
    const float* eval_ = (const float*)d_in[3];
    const float* w1    = (const float*)d_in[4];
    const float* w2    = (const float*)d_in[5];
    const float* ln1g  = (const float*)d_in[6];
    const float* ln1b  = (const float*)d_in[7];
    const float* ln2g  = (const float*)d_in[8];
    const float* ln2b  = (const float*)d_in[9];
    float* out = (float*)d_out;

    k_hist_scan<<<HS_BLOCKS, TILE_THREADS>>>(edst);
    k_scatter_cvt<<<(N_EDGES + 255) / 256, 256>>>(esrc, edst, eval_, x);

    int blocks = (N_NODES * 32 + 255) / 256;
    k_layer0<<<blocks, 256>>>(w1, ln1g, ln1b);
    k_layer1<<<blocks, 256>>>(w2, ln2g, ln2b, out);
}